// round 1
// baseline (speedup 1.0000x reference)
#include <cuda_runtime.h>
#include <math.h>

// GraphAttentionLayer: N=8192, FIN=128, F(OUT)=64
//   h  = inp @ W                         (8192x64)
//   s1 = h @ a1, s2 = h @ a2             (8192)
//   e  = leaky_relu(s1[i]+s2[j], 0.2)
//   att = softmax_row(where(adj>0, e, -1e12))
//   out = elu(att @ h)
//
// Kernel 1 (k_proj): h, s1, s2 into __device__ scratch.
// Kernel 2 (k_attn): flash-style fused masked softmax + GEMM.
//   Masked entries contribute exp(-1e12 - max) == 0 in the reference, so we
//   simply skip them; logits are bounded (|x| <~ 10) so no max subtraction
//   is needed for fp32 stability.

#define GAT_ALPHA 0.2f

constexpr int N_NODES = 8192;
constexpr int FIN     = 128;
constexpr int F       = 64;

constexpr int TI = 64;   // rows per block in k_attn
constexpr int TJ = 64;   // j-chunk per stage

__device__ float g_h[N_NODES * F];
__device__ float g_s1[N_NODES];
__device__ float g_s2[N_NODES];

// ---------------------------------------------------------------------------
// Kernel 1: h = inp @ W, s1 = h.a1, s2 = h.a2.  One block (64 threads) per row.
// ---------------------------------------------------------------------------
__global__ __launch_bounds__(64) void k_proj(const float* __restrict__ inp,
                                             const float* __restrict__ W,
                                             const float* __restrict__ a) {
    int i = blockIdx.x;
    int f = threadIdx.x;  // 0..63

    __shared__ float srow[FIN];
    __shared__ float sred[4];

    srow[f]      = inp[i * FIN + f];
    srow[f + 64] = inp[i * FIN + 64 + f];
    __syncthreads();

    float acc = 0.f;
#pragma unroll
    for (int k = 0; k < FIN; k++) {
        acc = fmaf(srow[k], __ldg(&W[k * F + f]), acc);
    }
    g_h[i * F + f] = acc;

    float p1 = acc * __ldg(&a[f]);       // a1[f]
    float p2 = acc * __ldg(&a[F + f]);   // a2[f]
#pragma unroll
    for (int off = 16; off > 0; off >>= 1) {
        p1 += __shfl_xor_sync(0xffffffffu, p1, off);
        p2 += __shfl_xor_sync(0xffffffffu, p2, off);
    }
    if ((f & 31) == 0) {
        sred[(f >> 5) * 2 + 0] = p1;
        sred[(f >> 5) * 2 + 1] = p2;
    }
    __syncthreads();
    if (f == 0) {
        g_s1[i] = sred[0] + sred[2];
        g_s2[i] = sred[1] + sred[3];
    }
}

// ---------------------------------------------------------------------------
// Kernel 2: fused masked softmax + (att @ h) + ELU.
// Grid: N/TI = 128 blocks, 256 threads.
// Thread map: tx = t&7 handles 8 features (fb = tx*8); ty = t>>3 handles
// rows ty and ty+32 of the 64-row block tile. Each thread keeps 2x8 fp32
// accumulators plus 2 softmax-denominator accumulators.
// ---------------------------------------------------------------------------
__global__ __launch_bounds__(256) void k_attn(const int* __restrict__ adj,
                                              float* __restrict__ out) {
    __shared__ float sW[TI][TJ + 1];   // attention weights tile (+1 pad: avoid conflicts)
    __shared__ float sH[TJ][F];        // h tile
    __shared__ float sS1[TI];

    const int t  = threadIdx.x;
    const int tx = t & 7;
    const int ty = t >> 3;
    const int fb = tx * 8;
    const int i0 = blockIdx.x * TI;

    if (t < TI) sS1[t] = g_s1[i0 + t];

    float acc0[8], acc1[8];
#pragma unroll
    for (int c = 0; c < 8; c++) { acc0[c] = 0.f; acc1[c] = 0.f; }
    float z0 = 0.f, z1 = 0.f;

    for (int jc = 0; jc < N_NODES; jc += TJ) {
        __syncthreads();  // previous compute done; also covers sS1 init on iter 0

        // ---- stage H tile: rows jc..jc+TJ-1 of g_h are contiguous ----
        {
            const float4* src = reinterpret_cast<const float4*>(g_h + (size_t)jc * F);
            float4* dst = reinterpret_cast<float4*>(&sH[0][0]);
#pragma unroll
            for (int r = 0; r < (TJ * F / 4) / 256; r++) {
                dst[t + r * 256] = src[t + r * 256];
            }
        }
        // ---- stage W tile: w[i][j] = adj ? exp(leaky_relu(s1_i + s2_j)) : 0 ----
#pragma unroll
        for (int r = 0; r < (TI * TJ) / 256; r++) {
            int idx = t + r * 256;
            int i = idx >> 6;        // /TJ
            int j = idx & (TJ - 1);
            int av = __ldg(&adj[(size_t)(i0 + i) * N_NODES + jc + j]);
            float x = sS1[i] + __ldg(&g_s2[jc + j]);
            float e = (x > 0.f) ? x : GAT_ALPHA * x;
            sW[i][j] = (av > 0) ? __expf(e) : 0.f;
        }
        __syncthreads();

        // ---- accumulate ----
#pragma unroll 4
        for (int jj = 0; jj < TJ; jj++) {
            float4 hA = *reinterpret_cast<const float4*>(&sH[jj][fb]);
            float4 hB = *reinterpret_cast<const float4*>(&sH[jj][fb + 4]);
            float h8[8] = {hA.x, hA.y, hA.z, hA.w, hB.x, hB.y, hB.z, hB.w};
            float w0 = sW[ty][jj];
            float w1 = sW[ty + 32][jj];
            z0 += w0;
            z1 += w1;
#pragma unroll
            for (int c = 0; c < 8; c++) {
                acc0[c] = fmaf(w0, h8[c], acc0[c]);
                acc1[c] = fmaf(w1, h8[c], acc1[c]);
            }
        }
    }

    // ---- epilogue: normalize + ELU + store ----
    // z0/z1 were accumulated identically by every tx-thread of the same row,
    // so no cross-thread reduction is needed.
    const float inv0 = 1.f / z0;
    const float inv1 = 1.f / z1;

    float4 o0a, o0b, o1a, o1b;
    float v;
    v = acc0[0] * inv0; o0a.x = v > 0.f ? v : expm1f(v);
    v = acc0[1] * inv0; o0a.y = v > 0.f ? v : expm1f(v);
    v = acc0[2] * inv0; o0a.z = v > 0.f ? v : expm1f(v);
    v = acc0[3] * inv0; o0a.w = v > 0.f ? v : expm1f(v);
    v = acc0[4] * inv0; o0b.x = v > 0.f ? v : expm1f(v);
    v = acc0[5] * inv0; o0b.y = v > 0.f ? v : expm1f(v);
    v = acc0[6] * inv0; o0b.z = v > 0.f ? v : expm1f(v);
    v = acc0[7] * inv0; o0b.w = v > 0.f ? v : expm1f(v);
    v = acc1[0] * inv1; o1a.x = v > 0.f ? v : expm1f(v);
    v = acc1[1] * inv1; o1a.y = v > 0.f ? v : expm1f(v);
    v = acc1[2] * inv1; o1a.z = v > 0.f ? v : expm1f(v);
    v = acc1[3] * inv1; o1a.w = v > 0.f ? v : expm1f(v);
    v = acc1[4] * inv1; o1b.x = v > 0.f ? v : expm1f(v);
    v = acc1[5] * inv1; o1b.y = v > 0.f ? v : expm1f(v);
    v = acc1[6] * inv1; o1b.z = v > 0.f ? v : expm1f(v);
    v = acc1[7] * inv1; o1b.w = v > 0.f ? v : expm1f(v);

    float4* outv0 = reinterpret_cast<float4*>(out + (size_t)(i0 + ty) * F + fb);
    float4* outv1 = reinterpret_cast<float4*>(out + (size_t)(i0 + ty + 32) * F + fb);
    outv0[0] = o0a;
    outv0[1] = o0b;
    outv1[0] = o1a;
    outv1[1] = o1b;
}

// ---------------------------------------------------------------------------
extern "C" void kernel_launch(void* const* d_in, const int* in_sizes, int n_in,
                              void* d_out, int out_size) {
    const float* inp = (const float*)d_in[0];   // [8192,128]
    const int*   adj = (const int*)d_in[1];     // [8192,8192]
    const float* W   = (const float*)d_in[2];   // [128,64]
    const float* a   = (const float*)d_in[3];   // [128,1]
    float* out = (float*)d_out;                 // [8192,64]

    k_proj<<<N_NODES, 64>>>(inp, W, a);
    k_attn<<<N_NODES / TI, 256>>>(adj, out);
}

// round 3
// speedup vs baseline: 6.8593x; 6.8593x over previous
#include <cuda_runtime.h>
#include <cuda_bf16.h>
#include <math.h>
#include <stdint.h>

// GraphAttentionLayer  N=8192, FIN=128, F=64  (sm_100-safe: mma.sync HMMA, no tcgen05)
//
//  w_ij = adj ? exp(leaky_relu(s1_i + s2_j)) : 0
//       = adj ? ( (u_i*v_j >= 1) ? u_i*v_j : u5_i*v5_j ) : 0      u=e^s1, u5=e^{0.2 s1}, ...
//  out_i = elu( (sum_j w_ij h_j) / (sum_j w_ij) )
//
// k_proj:    h = inp@W (fp32), u/u5/v/v5, h^T stored as exact bf16 hi/lo pair.
// k_attn:    128 blocks = 64 row-tiles x 2 j-halves, 256 threads.
//            Per 64-j chunk: cp.async-staged adj + H^T tiles (double buffered),
//            w-compute -> P tile (bf16 hi/lo, SW128) in SMEM, then per-warp
//            ldmatrix + mma.sync m16n8k16 bf16, 3 products (Ph*Hh + Ph*Hl + Pl*Hh),
//            fp32 accumulators held in registers across all 64 chunks.
// k_combine: out = elu((num0+num1)/(z0+z1)).

constexpr int N_NODES = 8192;
constexpr int FIN = 128;
constexpr int F = 64;

__device__ float g_u[N_NODES], g_u5[N_NODES], g_v[N_NODES], g_v5[N_NODES];
__device__ __nv_bfloat16 g_hThi[F][N_NODES];
__device__ __nv_bfloat16 g_hTlo[F][N_NODES];
__device__ float g_num[2][N_NODES][F];
__device__ float g_zp[2][N_NODES];

__device__ __forceinline__ uint32_t smem_u32(const void* p) {
    uint32_t a;
    asm("{ .reg .u64 t; cvta.to.shared.u64 t, %1; cvt.u32.u64 %0, t; }" : "=r"(a) : "l"(p));
    return a;
}
__device__ __forceinline__ uint32_t swz(uint32_t o) { return o ^ ((o >> 3) & 0x70); }

__device__ __forceinline__ void cp_async16(uint32_t dst, const void* src) {
    asm volatile("cp.async.cg.shared.global [%0], [%1], 16;" :: "r"(dst), "l"(src) : "memory");
}
__device__ __forceinline__ void cp_commit() {
    asm volatile("cp.async.commit_group;" ::: "memory");
}
__device__ __forceinline__ void cp_wait_all() {
    asm volatile("cp.async.wait_group 0;" ::: "memory");
}
__device__ __forceinline__ void ldsm_x4(uint32_t* r, uint32_t addr) {
    asm volatile("ldmatrix.sync.aligned.m8n8.x4.shared.b16 {%0,%1,%2,%3}, [%4];"
                 : "=r"(r[0]), "=r"(r[1]), "=r"(r[2]), "=r"(r[3]) : "r"(addr));
}
__device__ __forceinline__ void ldsm_x2(uint32_t* r, uint32_t addr) {
    asm volatile("ldmatrix.sync.aligned.m8n8.x2.shared.b16 {%0,%1}, [%2];"
                 : "=r"(r[0]), "=r"(r[1]) : "r"(addr));
}
__device__ __forceinline__ void mma16816(float* d, const uint32_t* a, const uint32_t* b) {
    asm volatile(
        "mma.sync.aligned.m16n8k16.row.col.f32.bf16.bf16.f32 "
        "{%0,%1,%2,%3}, {%4,%5,%6,%7}, {%8,%9}, {%0,%1,%2,%3};"
        : "+f"(d[0]), "+f"(d[1]), "+f"(d[2]), "+f"(d[3])
        : "r"(a[0]), "r"(a[1]), "r"(a[2]), "r"(a[3]), "r"(b[0]), "r"(b[1]));
}
__device__ __forceinline__ uint32_t cvt_bf16x2(float hi_val, float lo_val) {
    // packs {upper=hi_val, lower=lo_val}
    uint32_t d;
    asm("cvt.rn.bf16x2.f32 %0, %1, %2;" : "=r"(d) : "f"(hi_val), "f"(lo_val));
    return d;
}

// ---------------------------------------------------------------------------
// Kernel 1: projection. 128 blocks x 256 threads, 64 rows each.
// ---------------------------------------------------------------------------
constexpr int PROJ_PAD = 132;
constexpr int SM_PROJ = 64 * PROJ_PAD * 4 + FIN * F * 4 + 2 * FIN * 4;

__global__ __launch_bounds__(256, 1) void k_proj(const float* __restrict__ inp,
                                                 const float* __restrict__ W,
                                                 const float* __restrict__ a) {
    extern __shared__ char sm[];
    float* sIn = (float*)sm;                              // [64][132]
    float* sW  = (float*)(sm + 64 * PROJ_PAD * 4);        // [128][64]
    float* sA  = sW + FIN * F;                            // [128]

    const int t = threadIdx.x;
    const int i0 = blockIdx.x * 64;

    {
        const float4* src = (const float4*)(inp + (size_t)i0 * FIN);
#pragma unroll
        for (int r = 0; r < 8; r++) {
            int idx = t + r * 256;
            int row = idx >> 5, col = idx & 31;
            *(float4*)(sIn + row * PROJ_PAD + col * 4) = src[idx];
        }
    }
    {
        const float4* src = (const float4*)W;
        float4* dst = (float4*)sW;
#pragma unroll
        for (int r = 0; r < 8; r++) dst[t + r * 256] = src[t + r * 256];
    }
    if (t < 128) sA[t] = a[t];
    __syncthreads();

    const int tc = t & 15, tr = t >> 4;
    const int f0 = tc * 4, r0 = tr * 4;

    float acc[4][4] = {};
#pragma unroll 4
    for (int k = 0; k < FIN; k++) {
        float4 w4 = *(const float4*)(sW + k * F + f0);
#pragma unroll
        for (int rr = 0; rr < 4; rr++) {
            float x = sIn[(r0 + rr) * PROJ_PAD + k];
            acc[rr][0] = fmaf(x, w4.x, acc[rr][0]);
            acc[rr][1] = fmaf(x, w4.y, acc[rr][1]);
            acc[rr][2] = fmaf(x, w4.z, acc[rr][2]);
            acc[rr][3] = fmaf(x, w4.w, acc[rr][3]);
        }
    }

    float p1[4], p2[4];
#pragma unroll
    for (int rr = 0; rr < 4; rr++) {
        p1[rr] = acc[rr][0] * sA[f0] + acc[rr][1] * sA[f0 + 1] +
                 acc[rr][2] * sA[f0 + 2] + acc[rr][3] * sA[f0 + 3];
        p2[rr] = acc[rr][0] * sA[64 + f0] + acc[rr][1] * sA[64 + f0 + 1] +
                 acc[rr][2] * sA[64 + f0 + 2] + acc[rr][3] * sA[64 + f0 + 3];
#pragma unroll
        for (int m = 1; m < 16; m <<= 1) {
            p1[rr] += __shfl_xor_sync(0xffffffffu, p1[rr], m);
            p2[rr] += __shfl_xor_sync(0xffffffffu, p2[rr], m);
        }
    }
    if (tc == 0) {
#pragma unroll
        for (int rr = 0; rr < 4; rr++) {
            int i = i0 + r0 + rr;
            float s1 = p1[rr], s2 = p2[rr];
            g_u[i]  = expf(s1);
            g_u5[i] = expf(0.2f * s1);
            g_v[i]  = expf(s2);
            g_v5[i] = expf(0.2f * s2);
        }
    }

    __syncthreads();
    __nv_bfloat16* sThi = (__nv_bfloat16*)sm;        // [64 f][64 rows]
    __nv_bfloat16* sTlo = sThi + 64 * 64;
#pragma unroll
    for (int rr = 0; rr < 4; rr++)
#pragma unroll
        for (int c = 0; c < 4; c++) {
            float v = acc[rr][c];
            __nv_bfloat16 h = __float2bfloat16(v);
            __nv_bfloat16 l = __float2bfloat16(v - __bfloat162float(h));
            sThi[(f0 + c) * 64 + (r0 + rr)] = h;
            sTlo[(f0 + c) * 64 + (r0 + rr)] = l;
        }
    __syncthreads();
#pragma unroll
    for (int q = 0; q < 2; q++) {
        int c16 = t + q * 256;
        int f = c16 >> 3, col = c16 & 7;
        *(uint4*)((char*)&g_hThi[f][i0] + col * 16) = ((const uint4*)sThi)[c16];
        *(uint4*)((char*)&g_hTlo[f][i0] + col * 16) = ((const uint4*)sTlo)[c16];
    }
}

// ---------------------------------------------------------------------------
// Kernel 2: fused masked-weight + HMMA GEMM. 128 blocks x 256 threads.
// ---------------------------------------------------------------------------
constexpr int ADJ_PITCH = 272;                 // bytes per adj tile row (64 ints + 16B pad)
constexpr int SM_Z    = 0;                     // 128 fp32
constexpr int SM_P_HI = 1024;                  // 128x64 bf16, SW128  (16 KB)
constexpr int SM_P_LO = SM_P_HI + 16384;
constexpr int SM_H_HI = SM_P_LO + 16384;       // 2 bufs x 64x64 bf16 (8 KB each)
constexpr int SM_H_LO = SM_H_HI + 16384;
constexpr int SM_ADJ  = SM_H_LO + 16384;       // 2 bufs x 128 x 272B
constexpr int SM_V    = SM_ADJ + 2 * 128 * ADJ_PITCH;   // 4096 fp32
constexpr int SM_V5   = SM_V + 16384;
constexpr int SM_ATTN = SM_V5 + 16384;         // ~163 KB

__global__ __launch_bounds__(256, 1) void k_attn(const int* __restrict__ adj) {
    extern __shared__ char sm[];
    const uint32_t smb = smem_u32(sm);
    const int t = threadIdx.x;
    const int lane = t & 31;
    const int wid = t >> 5;
    const int rt = blockIdx.x >> 1, half = blockIdx.x & 1;
    const int i0 = rt * 128;
    const int j0 = half * 4096;
    const int row = t >> 1;              // 0..127 (w-compute row)
    const int jsub = (t & 1) * 32;       // this thread's 32 j's within chunk
    const int m0 = wid * 16;             // warp's output row block

    float* sV  = (float*)(sm + SM_V);
    float* sV5 = (float*)(sm + SM_V5);

    // stage v/v5 for this half (reused by all 64 chunks)
#pragma unroll
    for (int r = 0; r < 16; r++) {
        int idx = t + r * 256;
        sV[idx]  = g_v[j0 + idx];
        sV5[idx] = g_v5[j0 + idx];
    }

    const float u  = g_u[i0 + row];
    const float u5 = g_u5[i0 + row];

    // cp.async staging of one chunk (adj + H hi/lo) into buffer b
    auto stage = [&](int c, int b) {
        // H: 2 x 512 16B chunks
#pragma unroll
        for (int q = 0; q < 2; q++) {
            int c16 = t + q * 256;
            int f = c16 >> 3, col = c16 & 7;
            uint32_t off = swz((uint32_t)(f * 128 + col * 16));
            cp_async16(smb + SM_H_HI + b * 8192 + off,
                       (const char*)&g_hThi[f][j0 + c * 64] + col * 16);
            cp_async16(smb + SM_H_LO + b * 8192 + off,
                       (const char*)&g_hTlo[f][j0 + c * 64] + col * 16);
        }
        // adj: 2048 16B chunks (128 rows x 256B)
#pragma unroll
        for (int q = 0; q < 8; q++) {
            int idx = t + q * 256;
            int r = idx >> 4, col = idx & 15;
            cp_async16(smb + SM_ADJ + b * (128 * ADJ_PITCH) + r * ADJ_PITCH + col * 16,
                       (const char*)(adj + (size_t)(i0 + r) * N_NODES + j0 + c * 64) + col * 16);
        }
    };

    stage(0, 0);
    cp_commit();

    float acc[8][4] = {};
    float z = 0.f;

    for (int c = 0; c < 64; c++) {
        const int b = c & 1;

        cp_wait_all();
        __syncthreads();          // chunk c's adj+H visible to everyone; P free to overwrite

        if (c + 1 < 64) {
            stage(c + 1, b ^ 1);
            cp_commit();
        }

        // ---- w-compute: this thread -> 32 j's of row `row`; store P hi/lo (SW128) ----
        {
            const char* aRow = sm + SM_ADJ + b * (128 * ADJ_PITCH) + row * ADJ_PITCH + (t & 1) * 128;
            const float4* vp  = (const float4*)(sV  + c * 64 + jsub);
            const float4* v5p = (const float4*)(sV5 + c * 64 + jsub);
#pragma unroll
            for (int g = 0; g < 4; g++) {
                uint4 a0 = *(const uint4*)(aRow + g * 32);
                uint4 a1 = *(const uint4*)(aRow + g * 32 + 16);
                float4 v0 = vp[g * 2],  v1 = vp[g * 2 + 1];
                float4 q0 = v5p[g * 2], q1 = v5p[g * 2 + 1];
                float w[8];
                {
                    float t1, t2, s;
                    t1 = u * v0.x; t2 = u5 * q0.x; s = (t1 >= 1.f) ? t1 : t2; w[0] = a0.x ? s : 0.f;
                    t1 = u * v0.y; t2 = u5 * q0.y; s = (t1 >= 1.f) ? t1 : t2; w[1] = a0.y ? s : 0.f;
                    t1 = u * v0.z; t2 = u5 * q0.z; s = (t1 >= 1.f) ? t1 : t2; w[2] = a0.z ? s : 0.f;
                    t1 = u * v0.w; t2 = u5 * q0.w; s = (t1 >= 1.f) ? t1 : t2; w[3] = a0.w ? s : 0.f;
                    t1 = u * v1.x; t2 = u5 * q1.x; s = (t1 >= 1.f) ? t1 : t2; w[4] = a1.x ? s : 0.f;
                    t1 = u * v1.y; t2 = u5 * q1.y; s = (t1 >= 1.f) ? t1 : t2; w[5] = a1.y ? s : 0.f;
                    t1 = u * v1.z; t2 = u5 * q1.z; s = (t1 >= 1.f) ? t1 : t2; w[6] = a1.z ? s : 0.f;
                    t1 = u * v1.w; t2 = u5 * q1.w; s = (t1 >= 1.f) ? t1 : t2; w[7] = a1.w ? s : 0.f;
                }
                z += ((w[0] + w[1]) + (w[2] + w[3])) + ((w[4] + w[5]) + (w[6] + w[7]));

                uint32_t hi[4], lo[4];
#pragma unroll
                for (int p = 0; p < 4; p++) {
                    float w0 = w[2 * p], w1 = w[2 * p + 1];
                    uint32_t hp = cvt_bf16x2(w1, w0);                 // {hi=w1, lo=w0}
                    float h0 = __uint_as_float(hp << 16);
                    float h1 = __uint_as_float(hp & 0xFFFF0000u);
                    hi[p] = hp;
                    lo[p] = cvt_bf16x2(w1 - h1, w0 - h0);
                }
                uint32_t off = swz((uint32_t)(row * 128 + jsub * 2 + g * 16));
                *(uint4*)(sm + SM_P_HI + off) = make_uint4(hi[0], hi[1], hi[2], hi[3]);
                *(uint4*)(sm + SM_P_LO + off) = make_uint4(lo[0], lo[1], lo[2], lo[3]);
            }
        }

        __syncthreads();          // P tile visible

        // ---- HMMA: warp computes rows m0..m0+15, all 64 cols ----
        {
            const uint32_t hbase = smb + SM_H_HI + b * 8192;
            const uint32_t lbase = smb + SM_H_LO + b * 8192;
            const int l15 = lane & 15;
#pragma unroll
            for (int ks = 0; ks < 4; ks++) {
                uint32_t aoff = swz((uint32_t)(((m0 + (lane & 7) + (lane & 8)) << 7) +
                                               ks * 32 + (lane & 16)));
                uint32_t ah[4], al[4];
                ldsm_x4(ah, smb + SM_P_HI + aoff);
                ldsm_x4(al, smb + SM_P_LO + aoff);
#pragma unroll
                for (int nb = 0; nb < 8; nb++) {
                    uint32_t boff = swz((uint32_t)(nb * 1024 + ((l15 & 7) << 7) +
                                                   ks * 32 + ((l15 & 8) << 1)));
                    uint32_t bh[2], bl[2];
                    ldsm_x2(bh, hbase + boff);
                    ldsm_x2(bl, lbase + boff);
                    mma16816(acc[nb], ah, bh);
                    mma16816(acc[nb], ah, bl);
                    mma16816(acc[nb], al, bh);
                }
            }
        }
    }

    // ---- epilogue ----
    float zsum = z + __shfl_xor_sync(0xffffffffu, z, 1);
    if ((t & 1) == 0) g_zp[half][i0 + row] = zsum;

    const int r0 = i0 + m0 + (lane >> 2);
    const int col = (lane & 3) * 2;
#pragma unroll
    for (int nb = 0; nb < 8; nb++) {
        *(float2*)&g_num[half][r0][nb * 8 + col]     = make_float2(acc[nb][0], acc[nb][1]);
        *(float2*)&g_num[half][r0 + 8][nb * 8 + col] = make_float2(acc[nb][2], acc[nb][3]);
    }
}

// ---------------------------------------------------------------------------
// Kernel 3: combine halves + ELU
// ---------------------------------------------------------------------------
__global__ __launch_bounds__(256) void k_combine(float* __restrict__ out) {
    int idx = blockIdx.x * 256 + threadIdx.x;   // float4 index, 131072 total
    int i = idx >> 4;
    float zinv = 1.0f / (g_zp[0][i] + g_zp[1][i]);
    float4 n0 = ((const float4*)g_num[0])[idx];
    float4 n1 = ((const float4*)g_num[1])[idx];
    float4 o;
    float v;
    v = (n0.x + n1.x) * zinv; o.x = v > 0.f ? v : expm1f(v);
    v = (n0.y + n1.y) * zinv; o.y = v > 0.f ? v : expm1f(v);
    v = (n0.z + n1.z) * zinv; o.z = v > 0.f ? v : expm1f(v);
    v = (n0.w + n1.w) * zinv; o.w = v > 0.f ? v : expm1f(v);
    ((float4*)out)[idx] = o;
}

// ---------------------------------------------------------------------------
extern "C" void kernel_launch(void* const* d_in, const int* in_sizes, int n_in,
                              void* d_out, int out_size) {
    const float* inp = (const float*)d_in[0];   // [8192,128]
    const int*   adj = (const int*)d_in[1];     // [8192,8192]
    const float* W   = (const float*)d_in[2];   // [128,64]
    const float* a   = (const float*)d_in[3];   // [128,1]
    float* out = (float*)d_out;                 // [8192,64]

    cudaFuncSetAttribute(k_proj, cudaFuncAttributeMaxDynamicSharedMemorySize, SM_PROJ);
    cudaFuncSetAttribute(k_attn, cudaFuncAttributeMaxDynamicSharedMemorySize, SM_ATTN);

    k_proj<<<128, 256, SM_PROJ>>>(inp, W, a);
    k_attn<<<128, 256, SM_ATTN>>>(adj);
    k_combine<<<N_NODES * F / 4 / 256, 256>>>(out);
}

// round 4
// speedup vs baseline: 6.8647x; 1.0008x over previous
#include <cuda_runtime.h>
#include <cuda_bf16.h>
#include <math.h>
#include <stdint.h>

// GraphAttentionLayer  N=8192, FIN=128, F=64  (sm_100-safe: mma.sync HMMA, no tcgen05)
//
//  w_ij = adj ? exp(leaky_relu(s1_i + s2_j)) : 0
//       = adj ? ( (u_i*v_j >= 1) ? u_i*v_j : u5_i*v5_j ) : 0      u=e^s1, u5=e^{0.2 s1}, ...
//  out_i = elu( (sum_j w_ij h_j) / (sum_j w_ij) )
//
// k_proj:    h = inp@W (fp32), u/u5/v/v5, h^T stored as exact bf16 hi/lo pair.
// k_attn:    128 blocks = 64 row-tiles x 2 j-halves, 256 threads.
//            Per 64-j chunk: cp.async-staged adj + H^T tiles (double buffered),
//            w-compute -> P tile (bf16 hi/lo, SW128) in SMEM, then per-warp
//            ldmatrix + mma.sync m16n8k16 bf16, 3 products (Ph*Hh + Ph*Hl + Pl*Hh),
//            fp32 accumulators held in registers across all 64 chunks.
// k_combine: out = elu((num0+num1)/(z0+z1)).

constexpr int N_NODES = 8192;
constexpr int FIN = 128;
constexpr int F = 64;

__device__ float g_u[N_NODES], g_u5[N_NODES], g_v[N_NODES], g_v5[N_NODES];
__device__ __nv_bfloat16 g_hThi[F][N_NODES];
__device__ __nv_bfloat16 g_hTlo[F][N_NODES];
__device__ float g_num[2][N_NODES][F];
__device__ float g_zp[2][N_NODES];

__device__ __forceinline__ uint32_t smem_u32(const void* p) {
    uint32_t a;
    asm("{ .reg .u64 t; cvta.to.shared.u64 t, %1; cvt.u32.u64 %0, t; }" : "=r"(a) : "l"(p));
    return a;
}
__device__ __forceinline__ uint32_t swz(uint32_t o) { return o ^ ((o >> 3) & 0x70); }

__device__ __forceinline__ void cp_async16(uint32_t dst, const void* src) {
    asm volatile("cp.async.cg.shared.global [%0], [%1], 16;" :: "r"(dst), "l"(src) : "memory");
}
__device__ __forceinline__ void cp_commit() {
    asm volatile("cp.async.commit_group;" ::: "memory");
}
__device__ __forceinline__ void cp_wait_all() {
    asm volatile("cp.async.wait_group 0;" ::: "memory");
}
__device__ __forceinline__ void ldsm_x4(uint32_t* r, uint32_t addr) {
    asm volatile("ldmatrix.sync.aligned.m8n8.x4.shared.b16 {%0,%1,%2,%3}, [%4];"
                 : "=r"(r[0]), "=r"(r[1]), "=r"(r[2]), "=r"(r[3]) : "r"(addr));
}
__device__ __forceinline__ void ldsm_x2(uint32_t* r, uint32_t addr) {
    asm volatile("ldmatrix.sync.aligned.m8n8.x2.shared.b16 {%0,%1}, [%2];"
                 : "=r"(r[0]), "=r"(r[1]) : "r"(addr));
}
__device__ __forceinline__ void mma16816(float* d, const uint32_t* a, const uint32_t* b) {
    asm volatile(
        "mma.sync.aligned.m16n8k16.row.col.f32.bf16.bf16.f32 "
        "{%0,%1,%2,%3}, {%4,%5,%6,%7}, {%8,%9}, {%0,%1,%2,%3};"
        : "+f"(d[0]), "+f"(d[1]), "+f"(d[2]), "+f"(d[3])
        : "r"(a[0]), "r"(a[1]), "r"(a[2]), "r"(a[3]), "r"(b[0]), "r"(b[1]));
}
__device__ __forceinline__ uint32_t cvt_bf16x2(float hi_val, float lo_val) {
    // packs {upper=hi_val, lower=lo_val}
    uint32_t d;
    asm("cvt.rn.bf16x2.f32 %0, %1, %2;" : "=r"(d) : "f"(hi_val), "f"(lo_val));
    return d;
}

// ---------------------------------------------------------------------------
// Kernel 1: projection. 128 blocks x 256 threads, 64 rows each.
// ---------------------------------------------------------------------------
constexpr int PROJ_PAD = 132;
constexpr int SM_PROJ = 64 * PROJ_PAD * 4 + FIN * F * 4 + 2 * FIN * 4;

__global__ __launch_bounds__(256, 1) void k_proj(const float* __restrict__ inp,
                                                 const float* __restrict__ W,
                                                 const float* __restrict__ a) {
    extern __shared__ char sm[];
    float* sIn = (float*)sm;                              // [64][132]
    float* sW  = (float*)(sm + 64 * PROJ_PAD * 4);        // [128][64]
    float* sA  = sW + FIN * F;                            // [128]

    const int t = threadIdx.x;
    const int i0 = blockIdx.x * 64;

    {
        const float4* src = (const float4*)(inp + (size_t)i0 * FIN);
#pragma unroll
        for (int r = 0; r < 8; r++) {
            int idx = t + r * 256;
            int row = idx >> 5, col = idx & 31;
            *(float4*)(sIn + row * PROJ_PAD + col * 4) = src[idx];
        }
    }
    {
        const float4* src = (const float4*)W;
        float4* dst = (float4*)sW;
#pragma unroll
        for (int r = 0; r < 8; r++) dst[t + r * 256] = src[t + r * 256];
    }
    if (t < 128) sA[t] = a[t];
    __syncthreads();

    const int tc = t & 15, tr = t >> 4;
    const int f0 = tc * 4, r0 = tr * 4;

    float acc[4][4] = {};
#pragma unroll 4
    for (int k = 0; k < FIN; k++) {
        float4 w4 = *(const float4*)(sW + k * F + f0);
#pragma unroll
        for (int rr = 0; rr < 4; rr++) {
            float x = sIn[(r0 + rr) * PROJ_PAD + k];
            acc[rr][0] = fmaf(x, w4.x, acc[rr][0]);
            acc[rr][1] = fmaf(x, w4.y, acc[rr][1]);
            acc[rr][2] = fmaf(x, w4.z, acc[rr][2]);
            acc[rr][3] = fmaf(x, w4.w, acc[rr][3]);
        }
    }

    float p1[4], p2[4];
#pragma unroll
    for (int rr = 0; rr < 4; rr++) {
        p1[rr] = acc[rr][0] * sA[f0] + acc[rr][1] * sA[f0 + 1] +
                 acc[rr][2] * sA[f0 + 2] + acc[rr][3] * sA[f0 + 3];
        p2[rr] = acc[rr][0] * sA[64 + f0] + acc[rr][1] * sA[64 + f0 + 1] +
                 acc[rr][2] * sA[64 + f0 + 2] + acc[rr][3] * sA[64 + f0 + 3];
#pragma unroll
        for (int m = 1; m < 16; m <<= 1) {
            p1[rr] += __shfl_xor_sync(0xffffffffu, p1[rr], m);
            p2[rr] += __shfl_xor_sync(0xffffffffu, p2[rr], m);
        }
    }
    if (tc == 0) {
#pragma unroll
        for (int rr = 0; rr < 4; rr++) {
            int i = i0 + r0 + rr;
            float s1 = p1[rr], s2 = p2[rr];
            g_u[i]  = expf(s1);
            g_u5[i] = expf(0.2f * s1);
            g_v[i]  = expf(s2);
            g_v5[i] = expf(0.2f * s2);
        }
    }

    __syncthreads();
    __nv_bfloat16* sThi = (__nv_bfloat16*)sm;        // [64 f][64 rows]
    __nv_bfloat16* sTlo = sThi + 64 * 64;
#pragma unroll
    for (int rr = 0; rr < 4; rr++)
#pragma unroll
        for (int c = 0; c < 4; c++) {
            float v = acc[rr][c];
            __nv_bfloat16 h = __float2bfloat16(v);
            __nv_bfloat16 l = __float2bfloat16(v - __bfloat162float(h));
            sThi[(f0 + c) * 64 + (r0 + rr)] = h;
            sTlo[(f0 + c) * 64 + (r0 + rr)] = l;
        }
    __syncthreads();
#pragma unroll
    for (int q = 0; q < 2; q++) {
        int c16 = t + q * 256;
        int f = c16 >> 3, col = c16 & 7;
        *(uint4*)((char*)&g_hThi[f][i0] + col * 16) = ((const uint4*)sThi)[c16];
        *(uint4*)((char*)&g_hTlo[f][i0] + col * 16) = ((const uint4*)sTlo)[c16];
    }
}

// ---------------------------------------------------------------------------
// Kernel 2: fused masked-weight + HMMA GEMM. 128 blocks x 256 threads.
// ---------------------------------------------------------------------------
constexpr int ADJ_PITCH = 272;                 // bytes per adj tile row (64 ints + 16B pad)
constexpr int SM_Z    = 0;                     // 128 fp32
constexpr int SM_P_HI = 1024;                  // 128x64 bf16, SW128  (16 KB)
constexpr int SM_P_LO = SM_P_HI + 16384;
constexpr int SM_H_HI = SM_P_LO + 16384;       // 2 bufs x 64x64 bf16 (8 KB each)
constexpr int SM_H_LO = SM_H_HI + 16384;
constexpr int SM_ADJ  = SM_H_LO + 16384;       // 2 bufs x 128 x 272B
constexpr int SM_V    = SM_ADJ + 2 * 128 * ADJ_PITCH;   // 4096 fp32
constexpr int SM_V5   = SM_V + 16384;
constexpr int SM_ATTN = SM_V5 + 16384;         // ~163 KB

__global__ __launch_bounds__(256, 1) void k_attn(const int* __restrict__ adj) {
    extern __shared__ char sm[];
    const uint32_t smb = smem_u32(sm);
    const int t = threadIdx.x;
    const int lane = t & 31;
    const int wid = t >> 5;
    const int rt = blockIdx.x >> 1, half = blockIdx.x & 1;
    const int i0 = rt * 128;
    const int j0 = half * 4096;
    const int row = t >> 1;              // 0..127 (w-compute row)
    const int jsub = (t & 1) * 32;       // this thread's 32 j's within chunk
    const int m0 = wid * 16;             // warp's output row block

    float* sV  = (float*)(sm + SM_V);
    float* sV5 = (float*)(sm + SM_V5);

    // stage v/v5 for this half (reused by all 64 chunks)
#pragma unroll
    for (int r = 0; r < 16; r++) {
        int idx = t + r * 256;
        sV[idx]  = g_v[j0 + idx];
        sV5[idx] = g_v5[j0 + idx];
    }

    const float u  = g_u[i0 + row];
    const float u5 = g_u5[i0 + row];

    // cp.async staging of one chunk (adj + H hi/lo) into buffer b
    auto stage = [&](int c, int b) {
        // H: 2 x 512 16B chunks
#pragma unroll
        for (int q = 0; q < 2; q++) {
            int c16 = t + q * 256;
            int f = c16 >> 3, col = c16 & 7;
            uint32_t off = swz((uint32_t)(f * 128 + col * 16));
            cp_async16(smb + SM_H_HI + b * 8192 + off,
                       (const char*)&g_hThi[f][j0 + c * 64] + col * 16);
            cp_async16(smb + SM_H_LO + b * 8192 + off,
                       (const char*)&g_hTlo[f][j0 + c * 64] + col * 16);
        }
        // adj: 2048 16B chunks (128 rows x 256B)
#pragma unroll
        for (int q = 0; q < 8; q++) {
            int idx = t + q * 256;
            int r = idx >> 4, col = idx & 15;
            cp_async16(smb + SM_ADJ + b * (128 * ADJ_PITCH) + r * ADJ_PITCH + col * 16,
                       (const char*)(adj + (size_t)(i0 + r) * N_NODES + j0 + c * 64) + col * 16);
        }
    };

    stage(0, 0);
    cp_commit();

    float acc[8][4] = {};
    float z = 0.f;

    for (int c = 0; c < 64; c++) {
        const int b = c & 1;

        cp_wait_all();
        __syncthreads();          // chunk c's adj+H visible to everyone; P free to overwrite

        if (c + 1 < 64) {
            stage(c + 1, b ^ 1);
            cp_commit();
        }

        // ---- w-compute: this thread -> 32 j's of row `row`; store P hi/lo (SW128) ----
        {
            const char* aRow = sm + SM_ADJ + b * (128 * ADJ_PITCH) + row * ADJ_PITCH + (t & 1) * 128;
            const float4* vp  = (const float4*)(sV  + c * 64 + jsub);
            const float4* v5p = (const float4*)(sV5 + c * 64 + jsub);
#pragma unroll
            for (int g = 0; g < 4; g++) {
                uint4 a0 = *(const uint4*)(aRow + g * 32);
                uint4 a1 = *(const uint4*)(aRow + g * 32 + 16);
                float4 v0 = vp[g * 2],  v1 = vp[g * 2 + 1];
                float4 q0 = v5p[g * 2], q1 = v5p[g * 2 + 1];
                float w[8];
                {
                    float t1, t2, s;
                    t1 = u * v0.x; t2 = u5 * q0.x; s = (t1 >= 1.f) ? t1 : t2; w[0] = a0.x ? s : 0.f;
                    t1 = u * v0.y; t2 = u5 * q0.y; s = (t1 >= 1.f) ? t1 : t2; w[1] = a0.y ? s : 0.f;
                    t1 = u * v0.z; t2 = u5 * q0.z; s = (t1 >= 1.f) ? t1 : t2; w[2] = a0.z ? s : 0.f;
                    t1 = u * v0.w; t2 = u5 * q0.w; s = (t1 >= 1.f) ? t1 : t2; w[3] = a0.w ? s : 0.f;
                    t1 = u * v1.x; t2 = u5 * q1.x; s = (t1 >= 1.f) ? t1 : t2; w[4] = a1.x ? s : 0.f;
                    t1 = u * v1.y; t2 = u5 * q1.y; s = (t1 >= 1.f) ? t1 : t2; w[5] = a1.y ? s : 0.f;
                    t1 = u * v1.z; t2 = u5 * q1.z; s = (t1 >= 1.f) ? t1 : t2; w[6] = a1.z ? s : 0.f;
                    t1 = u * v1.w; t2 = u5 * q1.w; s = (t1 >= 1.f) ? t1 : t2; w[7] = a1.w ? s : 0.f;
                }
                z += ((w[0] + w[1]) + (w[2] + w[3])) + ((w[4] + w[5]) + (w[6] + w[7]));

                uint32_t hi[4], lo[4];
#pragma unroll
                for (int p = 0; p < 4; p++) {
                    float w0 = w[2 * p], w1 = w[2 * p + 1];
                    uint32_t hp = cvt_bf16x2(w1, w0);                 // {hi=w1, lo=w0}
                    float h0 = __uint_as_float(hp << 16);
                    float h1 = __uint_as_float(hp & 0xFFFF0000u);
                    hi[p] = hp;
                    lo[p] = cvt_bf16x2(w1 - h1, w0 - h0);
                }
                uint32_t off = swz((uint32_t)(row * 128 + jsub * 2 + g * 16));
                *(uint4*)(sm + SM_P_HI + off) = make_uint4(hi[0], hi[1], hi[2], hi[3]);
                *(uint4*)(sm + SM_P_LO + off) = make_uint4(lo[0], lo[1], lo[2], lo[3]);
            }
        }

        __syncthreads();          // P tile visible

        // ---- HMMA: warp computes rows m0..m0+15, all 64 cols ----
        {
            const uint32_t hbase = smb + SM_H_HI + b * 8192;
            const uint32_t lbase = smb + SM_H_LO + b * 8192;
            const int l15 = lane & 15;
#pragma unroll
            for (int ks = 0; ks < 4; ks++) {
                uint32_t aoff = swz((uint32_t)(((m0 + (lane & 7) + (lane & 8)) << 7) +
                                               ks * 32 + (lane & 16)));
                uint32_t ah[4], al[4];
                ldsm_x4(ah, smb + SM_P_HI + aoff);
                ldsm_x4(al, smb + SM_P_LO + aoff);
#pragma unroll
                for (int nb = 0; nb < 8; nb++) {
                    uint32_t boff = swz((uint32_t)(nb * 1024 + ((l15 & 7) << 7) +
                                                   ks * 32 + ((l15 & 8) << 1)));
                    uint32_t bh[2], bl[2];
                    ldsm_x2(bh, hbase + boff);
                    ldsm_x2(bl, lbase + boff);
                    mma16816(acc[nb], ah, bh);
                    mma16816(acc[nb], ah, bl);
                    mma16816(acc[nb], al, bh);
                }
            }
        }
    }

    // ---- epilogue ----
    float zsum = z + __shfl_xor_sync(0xffffffffu, z, 1);
    if ((t & 1) == 0) g_zp[half][i0 + row] = zsum;

    const int r0 = i0 + m0 + (lane >> 2);
    const int col = (lane & 3) * 2;
#pragma unroll
    for (int nb = 0; nb < 8; nb++) {
        *(float2*)&g_num[half][r0][nb * 8 + col]     = make_float2(acc[nb][0], acc[nb][1]);
        *(float2*)&g_num[half][r0 + 8][nb * 8 + col] = make_float2(acc[nb][2], acc[nb][3]);
    }
}

// ---------------------------------------------------------------------------
// Kernel 3: combine halves + ELU
// ---------------------------------------------------------------------------
__global__ __launch_bounds__(256) void k_combine(float* __restrict__ out) {
    int idx = blockIdx.x * 256 + threadIdx.x;   // float4 index, 131072 total
    int i = idx >> 4;
    float zinv = 1.0f / (g_zp[0][i] + g_zp[1][i]);
    float4 n0 = ((const float4*)g_num[0])[idx];
    float4 n1 = ((const float4*)g_num[1])[idx];
    float4 o;
    float v;
    v = (n0.x + n1.x) * zinv; o.x = v > 0.f ? v : expm1f(v);
    v = (n0.y + n1.y) * zinv; o.y = v > 0.f ? v : expm1f(v);
    v = (n0.z + n1.z) * zinv; o.z = v > 0.f ? v : expm1f(v);
    v = (n0.w + n1.w) * zinv; o.w = v > 0.f ? v : expm1f(v);
    ((float4*)out)[idx] = o;
}

// ---------------------------------------------------------------------------
extern "C" void kernel_launch(void* const* d_in, const int* in_sizes, int n_in,
                              void* d_out, int out_size) {
    const float* inp = (const float*)d_in[0];   // [8192,128]
    const int*   adj = (const int*)d_in[1];     // [8192,8192]
    const float* W   = (const float*)d_in[2];   // [128,64]
    const float* a   = (const float*)d_in[3];   // [128,1]
    float* out = (float*)d_out;                 // [8192,64]

    cudaFuncSetAttribute(k_proj, cudaFuncAttributeMaxDynamicSharedMemorySize, SM_PROJ);
    cudaFuncSetAttribute(k_attn, cudaFuncAttributeMaxDynamicSharedMemorySize, SM_ATTN);

    k_proj<<<128, 256, SM_PROJ>>>(inp, W, a);
    k_attn<<<128, 256, SM_ATTN>>>(adj);
    k_combine<<<N_NODES * F / 4 / 256, 256>>>(out);
}